// round 10
// baseline (speedup 1.0000x reference)
#include <cuda_runtime.h>
#include <cuda_bf16.h>

#define NBINS 15
#define THREADS 256
#define WARPS (THREADS / 32)
#define MAXBLOCKS 592            // 4 blocks/SM * 148 SMs

// Global scratch (allocation-free). Zero at module load; finalizing block
// resets after each use so every graph replay sees zeros.
__device__ float    g_cnt[NBINS];
__device__ float    g_err[NBINS];
__device__ float    g_su[NBINS];
__device__ unsigned g_done;

#define FIXSCALE 16777216.0f     // 2^24
#define INVFIX   (1.0f / 16777216.0f)

// Per-row: u (collision entropy), err, bin (0..14 valid, 15 = invalid slot).
__device__ __forceinline__ void process_row(const float* __restrict__ r, int label,
                                            int& bin_sel, float& u, unsigned& err) {
    // max (error check only; sums need no stabilization: |logit| <~ 30).
    float m0 = fmaxf(r[0], r[1]), m1 = fmaxf(r[2], r[3]);
    float m2 = fmaxf(r[4], r[5]), m3 = fmaxf(r[6], r[7]);
    float m4 = fmaxf(r[8], r[9]);
    float m = fmaxf(fmaxf(fmaxf(m0, m1), fmaxf(m2, m3)), m4);

    // r[label] via binary selection tree on label bits (label in [0,10)).
    bool bb0 = label & 1, bb1 = label & 2, bb2 = label & 4, bb3 = label & 8;
    float t0 = bb0 ? r[1] : r[0];
    float t1 = bb0 ? r[3] : r[2];
    float t2 = bb0 ? r[5] : r[4];
    float t3 = bb0 ? r[7] : r[6];
    float t4 = bb0 ? r[9] : r[8];
    float s0 = bb1 ? t1 : t0;
    float s1 = bb1 ? t3 : t2;
    float q0 = bb2 ? s1 : s0;
    float rl = bb3 ? t4 : q0;    // labels 8,9 have bits1,2 = 0

    // two partial accumulators each -> half-length dependency chains
    float Sa = 0.0f, Sb = 0.0f, Qa = 0.0f, Qb = 0.0f;
#pragma unroll
    for (int j = 0; j < 10; j += 2) {
        float ea = __expf(r[j]);
        float eb = __expf(r[j + 1]);
        Sa += ea; Sb += eb;
        Qa = fmaf(ea, ea, Qa);
        Qb = fmaf(eb, eb, Qb);
    }
    float S = Sa + Sb, Q = Qa + Qb;

    // u = -log2(Q/S^2) = 2*log2(S) - log2(Q).  (Q/S^2 >= 0.1, eps irrelevant)
    u = fmaf(2.0f, __log2f(S), -__log2f(Q));
    err = (rl != m) ? 1u : 0u;   // first-argmax==label iff r[label]==max

    int b = (int)floorf(u * 15.0f);
    bool valid = (u >= 0.0f) && (u < 1.0f);
    bin_sel = valid ? b : NBINS; // invalid -> slot 15 (discarded)
}

__device__ __forceinline__ void hist_update(uint2* mycol, int b, float u, unsigned e) {
    uint2 v = mycol[b * 32];
    v.x += (unsigned)(int)(u * FIXSCALE);
    v.y += 1u | (e << 16);
    mycol[b * 32] = v;
}

__global__ __launch_bounds__(THREADS, 4)
void uce_fused_kernel(const float4* __restrict__ L4, const int2* __restrict__ lab2,
                      int P /* pairs */, int N, float* __restrict__ out) {
    // Per-(warp,lane) histogram: bank index == lane -> conflict-free.
    __shared__ uint2 s_hist[WARPS][NBINS + 1][32];
    __shared__ float    s_su[WARPS][NBINS];
    __shared__ unsigned s_ce[WARPS][NBINS];

    const int lane = threadIdx.x & 31;
    const int wid  = threadIdx.x >> 5;

    {
        uint2* h = &s_hist[0][0][0];
        const int tot = WARPS * (NBINS + 1) * 32;
        for (int i = threadIdx.x; i < tot; i += THREADS) h[i] = make_uint2(0u, 0u);
    }
    __syncthreads();

    uint2* mycol = &s_hist[wid][0][lane];   // stride between bins: 32 uint2

    const int stride = gridDim.x * blockDim.x;
    for (int p = blockIdx.x * blockDim.x + threadIdx.x; p < P; p += stride) {
        // 2 rows = 20 floats = 5 float4 (80B, 16B-aligned), batched up front.
        float4 a0 = L4[5 * p + 0];
        float4 a1 = L4[5 * p + 1];
        float4 a2 = L4[5 * p + 2];
        float4 a3 = L4[5 * p + 3];
        float4 a4 = L4[5 * p + 4];
        int2 lb = lab2[p];

        float f[20] = {a0.x, a0.y, a0.z, a0.w,
                       a1.x, a1.y, a1.z, a1.w,
                       a2.x, a2.y, a2.z, a2.w,
                       a3.x, a3.y, a3.z, a3.w,
                       a4.x, a4.y, a4.z, a4.w};

        int b0, b1; float u0, u1; unsigned e0, e1;
        process_row(f,      lb.x, b0, u0, e0);
        process_row(f + 10, lb.y, b1, u1, e1);

        hist_update(mycol, b0, u0, e0);
        hist_update(mycol, b1, u1, e1);
    }

    // Tail row if N odd.
    if ((N & 1) && blockIdx.x == 0 && threadIdx.x == 0) {
        const float* Lf  = (const float*)L4;
        const int*  labf = (const int*)lab2;
        float f[10];
#pragma unroll
        for (int j = 0; j < 10; j++) f[j] = Lf[(long long)(N - 1) * 10 + j];
        int b; float u; unsigned e;
        process_row(f, labf[N - 1], b, u, e);
        hist_update(mycol, b, u, e);
    }
    __syncthreads();

    // ---- Flush: per-bin warp shuffle reduce -> smem -> global atomics ----
#pragma unroll
    for (int j = 0; j < NBINS; j++) {
        uint2 v = s_hist[wid][j][lane];
        float    s = (float)v.x * INVFIX;
        unsigned c = v.y;
#pragma unroll
        for (int off = 16; off > 0; off >>= 1) {
            s += __shfl_down_sync(0xFFFFFFFFu, s, off);
            c += __shfl_down_sync(0xFFFFFFFFu, c, off);
        }
        if (lane == 0) { s_su[wid][j] = s; s_ce[wid][j] = c; }
    }
    __syncthreads();

    if (threadIdx.x < NBINS) {
        int j = threadIdx.x;
        float    s = 0.0f;
        unsigned cnt = 0u, er = 0u;
#pragma unroll
        for (int w = 0; w < WARPS; w++) {
            s += s_su[w][j];
            unsigned c = s_ce[w][j];
            cnt += (c & 0xFFFFu);
            er  += (c >> 16);
        }
        if (cnt > 0u) {
            atomicAdd(&g_su[j],  s);
            atomicAdd(&g_cnt[j], (float)cnt);
            atomicAdd(&g_err[j], (float)er);
        }
    }
    __syncthreads();

    // ---- Last block finalizes + resets scratch (graph-replay safe) ----
    if (threadIdx.x == 0) {
        __threadfence();
        unsigned ticket = atomicAdd(&g_done, 1u);
        if (ticket == gridDim.x - 1) {
            float n = (float)N;
            float loss = 0.0f;
#pragma unroll
            for (int b = 0; b < NBINS; b++) {
                float c = g_cnt[b];
                float pi = c / n;
                float cnt = (c > 0.0f) ? c : 1.0f;
                float ub  = g_su[b]  / cnt;
                float eb  = g_err[b] / cnt;
                float inner = 2.0f * exp2f(-ub) - 1.0f;
                inner = (inner < 0.0f) ? 0.0f : inner;
                float rr = 0.5f * (1.0f - sqrtf(inner));
                if (c > 0.0f) loss += fabsf(eb - rr) * pi;
                g_cnt[b] = 0.0f; g_err[b] = 0.0f; g_su[b] = 0.0f;
            }
            out[0] = loss;
            g_done = 0u;
            __threadfence();
        }
    }
}

extern "C" void kernel_launch(void* const* d_in, const int* in_sizes, int n_in,
                              void* d_out, int out_size) {
    const float* logits = (const float*)d_in[0];
    const int*   labels = (const int*)d_in[1];
    float* out = (float*)d_out;

    int N = in_sizes[1];      // labels element count
    int P = N / 2;            // sample pairs

    int blocks = (P + THREADS - 1) / THREADS;
    if (blocks > MAXBLOCKS) blocks = MAXBLOCKS;
    if (blocks < 1) blocks = 1;

    uce_fused_kernel<<<blocks, THREADS>>>(
        (const float4*)logits, (const int2*)labels, P, N, out);
}